// round 2
// baseline (speedup 1.0000x reference)
#include <cuda_runtime.h>
#include <cstdint>

// Problem shape (fixed by the reference): B=32, T=1000, D=512.
#define T_FRAMES 1000
#define D_DIM    512
#define NSTEP    (T_FRAMES - 1)
#define LANES    32
#define ELPL     (D_DIM / LANES)     // 16 floats per lane = 4 x float4

// Portable warp-wide float add reduction (redux.f32 is NOT available on
// plain compute_103 ptxas target — learned in R1).
__device__ __forceinline__ float warp_sum(float v) {
    #pragma unroll
    for (int m = 16; m > 0; m >>= 1)
        v += __shfl_xor_sync(0xffffffffu, v, m);
    return v;
}

__global__ void __launch_bounds__(LANES, 1)
distagg_scan_kernel(const float* __restrict__ data,
                    const float* __restrict__ thr_p,
                    float* __restrict__ out_means,
                    float* __restrict__ out_flags)
{
    __shared__ float s_thr2[T_FRAMES];   // (thr * factor(f))^2, sign-safe
    __shared__ float s_inv[T_FRAMES];    // 1/len

    const int b   = blockIdx.x;
    const int lid = threadIdx.x;

    const float thr = thr_p[0];

    // Tables: factor(f) = 1.9/(1+exp(clip(f - 1, -80, 80))) + 0.4
    for (int t = lid; t < T_FRAMES; t += LANES) {
        float a = fminf(fmaxf((float)t - 1.0f, -80.0f), 80.0f);
        float fac = 1.9f / (1.0f + expf(a)) + 0.4f;
        float te  = thr * fac;
        s_thr2[t] = (te >= 0.0f) ? te * te : -1.0f;  // compare dist^2 > te^2
        s_inv[t]  = (t > 0) ? (1.0f / (float)t) : 0.0f;
    }
    __syncthreads();

    // Each lane owns 16 consecutive floats of the feature dim.
    const float* __restrict__ dp = data
        + (size_t)b * T_FRAMES * D_DIM + (size_t)lid * ELPL;
    float* __restrict__ mp = out_means
        + (size_t)b * NSTEP * D_DIM + (size_t)lid * ELPL;
    float* __restrict__ fp = out_flags + (size_t)b * NSTEP;

    // Frame ring: cur = frame i, n1 = i+1, n2 = i+2; load i+3 each step.
    float4 rep[4], seg[4], cur[4], n1[4], n2[4];
    #pragma unroll
    for (int j = 0; j < 4; ++j) {
        rep[j] = *(const float4*)(dp + 4 * j);
        seg[j] = rep[j];
        cur[j] = *(const float4*)(dp + 1 * (size_t)D_DIM + 4 * j);
        n1[j]  = *(const float4*)(dp + 2 * (size_t)D_DIM + 4 * j);
        n2[j]  = *(const float4*)(dp + 3 * (size_t)D_DIM + 4 * j);
    }

    int   ind   = 0;
    float te2   = s_thr2[0];   // f at step 1 is 0
    float inv_c = s_inv[1];

    #pragma unroll 1
    for (int i = 1; i < T_FRAMES; ++i) {
        // Prefetch frame i+3 (clamped; duplicate loads of the last frame are
        // L1 hits and harmless).
        int r3 = i + 3;
        if (r3 > T_FRAMES - 1) r3 = T_FRAMES - 1;
        float4 nn[4];
        #pragma unroll
        for (int j = 0; j < 4; ++j)
            nn[j] = *(const float4*)(dp + (size_t)r3 * D_DIM + 4 * j);

        // Partial squared distance over this lane's 16 elements,
        // 4 independent accumulators to keep the FMA chain shallow.
        float a0 = 0.f, a1 = 0.f, a2 = 0.f, a3 = 0.f;
        #pragma unroll
        for (int j = 0; j < 4; ++j) {
            float dx = cur[j].x - rep[j].x;
            float dy = cur[j].y - rep[j].y;
            float dz = cur[j].z - rep[j].z;
            float dw = cur[j].w - rep[j].w;
            a0 = fmaf(dx, dx, a0);
            a1 = fmaf(dy, dy, a1);
            a2 = fmaf(dz, dz, a2);
            a3 = fmaf(dw, dw, a3);
        }
        float dist2 = warp_sum((a0 + a1) + (a2 + a3));

        const bool  bnd = dist2 > te2;
        const float inv = bnd ? inv_c : 0.0f;   // exact zeros on non-boundary

        // Output row i-1.
        float* orow = mp + (size_t)(i - 1) * D_DIM;
        #pragma unroll
        for (int j = 0; j < 4; ++j) {
            float4 o;
            o.x = seg[j].x * inv;
            o.y = seg[j].y * inv;
            o.z = seg[j].z * inv;
            o.w = seg[j].w * inv;
            *(float4*)(orow + 4 * j) = o;
        }
        if (lid == 0) fp[i - 1] = bnd ? 1.0f : 0.0f;

        // State update (warp-uniform predicate -> SELs, no divergence).
        #pragma unroll
        for (int j = 0; j < 4; ++j) {
            rep[j].x = bnd ? cur[j].x : rep[j].x;
            rep[j].y = bnd ? cur[j].y : rep[j].y;
            rep[j].z = bnd ? cur[j].z : rep[j].z;
            rep[j].w = bnd ? cur[j].w : rep[j].w;
            seg[j].x = bnd ? cur[j].x : seg[j].x + cur[j].x;
            seg[j].y = bnd ? cur[j].y : seg[j].y + cur[j].y;
            seg[j].z = bnd ? cur[j].z : seg[j].z + cur[j].z;
            seg[j].w = bnd ? cur[j].w : seg[j].w + cur[j].w;
        }
        ind = bnd ? i : ind;

        // Next step's table entries, fetched off the critical path.
        const int f_next = i - ind;          // 0 if boundary just fired
        te2   = s_thr2[f_next];
        inv_c = s_inv[f_next + 1];

        // Rotate the frame ring.
        #pragma unroll
        for (int j = 0; j < 4; ++j) {
            cur[j] = n1[j];
            n1[j]  = n2[j];
            n2[j]  = nn[j];
        }
    }
}

extern "C" void kernel_launch(void* const* d_in, const int* in_sizes, int n_in,
                              void* d_out, int out_size) {
    const float* data = (const float*)d_in[0];
    const float* thr  = (const float*)d_in[1];

    const int B = in_sizes[0] / (T_FRAMES * D_DIM);

    float* out   = (float*)d_out;
    float* means = out;                                // [B, 999, 512]
    float* flags = out + (size_t)B * NSTEP * D_DIM;    // [B, 999] as 0.0/1.0

    (void)n_in; (void)out_size;
    distagg_scan_kernel<<<B, LANES>>>(data, thr, means, flags);
}

// round 3
// speedup vs baseline: 5.3703x; 5.3703x over previous
#include <cuda_runtime.h>
#include <cstdint>

// Problem shape (fixed by the reference): B=32, T=1000, D=512.
#define TT   1000
#define DD   512
#define NS   999         // steps / output rows
#define KJ   8           // max precomputed back-distance
#define AC   16          // kernel-A i-chunk
#define NCH  ((NS + AC - 1) / AC)   // 63
#define MAXB 32

// Scratch (no allocations allowed -> __device__ globals).
__device__ float g_D2[MAXB * TT * KJ];   // D2[b][i][j-1] = ||x_i - x_{i-j}||^2
__device__ int   g_ind[MAXB * TT];       // segment-start index per step (valid when flag)

// ---------------------------------------------------------------------------
// Kernel A: banded pairwise squared distances, smem-tiled.
// grid = B * NCH, block = 256 (8 warps, 2 i's per warp).
// ---------------------------------------------------------------------------
__global__ void __launch_bounds__(256, 1)
kA(const float* __restrict__ data)
{
    __shared__ float fr[(AC + KJ) * DD];          // 24 frames * 2KB = 48KB
    const int b     = blockIdx.x / NCH;
    const int chunk = blockIdx.x % NCH;
    const int c0    = 1 + chunk * AC;             // first i of this chunk
    const int base  = c0 - KJ;                    // first frame needed (can be <0)

    const float4* dglob = (const float4*)(data + (size_t)b * TT * DD);
    float4* frv = (float4*)fr;
    for (int s = threadIdx.x; s < (AC + KJ) * (DD / 4); s += 256) {
        const int f  = s >> 7;                    // /128 float4 per frame
        const int w  = s & 127;
        const int fi = base + f;
        if (fi >= 0 && fi < TT)
            frv[s] = dglob[(size_t)fi * (DD / 4) + w];
    }
    __syncthreads();

    const int wid = threadIdx.x >> 5, lid = threadIdx.x & 31;
    #pragma unroll
    for (int u = 0; u < 2; ++u) {
        const int ii = wid + u * 8;               // 0..15, warp-uniform
        const int i  = c0 + ii;
        if (i > NS) continue;
        const int si = ii + KJ;                   // smem slot of frame i

        // Lane-interleaved (coalesced, conflict-free); distances are
        // permutation-invariant over the feature dim, so any consistent
        // lane->element map is fine.
        float4 x0 = frv[si * 128 +       lid];
        float4 x1 = frv[si * 128 + 32  + lid];
        float4 x2 = frv[si * 128 + 64  + lid];
        float4 x3 = frv[si * 128 + 96  + lid];

        float acc[KJ];
        #pragma unroll
        for (int j = 1; j <= KJ; ++j) {
            float a0 = 0.f, a1 = 0.f;
            if (i - j >= 0) {
                const int sj = si - j;
                float4 y;
                y = frv[sj * 128 + lid];
                { float dx=x0.x-y.x, dy=x0.y-y.y, dz=x0.z-y.z, dw=x0.w-y.w;
                  a0 = fmaf(dx,dx,fmaf(dy,dy,0.f)); a1 = fmaf(dz,dz,fmaf(dw,dw,0.f)); }
                y = frv[sj * 128 + 32 + lid];
                { float dx=x1.x-y.x, dy=x1.y-y.y, dz=x1.z-y.z, dw=x1.w-y.w;
                  a0 = fmaf(dx,dx,fmaf(dy,dy,a0)); a1 = fmaf(dz,dz,fmaf(dw,dw,a1)); }
                y = frv[sj * 128 + 64 + lid];
                { float dx=x2.x-y.x, dy=x2.y-y.y, dz=x2.z-y.z, dw=x2.w-y.w;
                  a0 = fmaf(dx,dx,fmaf(dy,dy,a0)); a1 = fmaf(dz,dz,fmaf(dw,dw,a1)); }
                y = frv[sj * 128 + 96 + lid];
                { float dx=x3.x-y.x, dy=x3.y-y.y, dz=x3.z-y.z, dw=x3.w-y.w;
                  a0 = fmaf(dx,dx,fmaf(dy,dy,a0)); a1 = fmaf(dz,dz,fmaf(dw,dw,a1)); }
            }
            acc[j - 1] = a0 + a1;
        }
        #pragma unroll
        for (int m = 16; m; m >>= 1) {
            #pragma unroll
            for (int k = 0; k < KJ; ++k)
                acc[k] += __shfl_xor_sync(0xffffffffu, acc[k], m);
        }
        if (lid == 0) {
            float4* o = (float4*)&g_D2[((size_t)b * TT + i) * KJ];
            o[0] = make_float4(acc[0], acc[1], acc[2], acc[3]);
            o[1] = make_float4(acc[4], acc[5], acc[6], acc[7]);
        }
    }
}

// ---------------------------------------------------------------------------
// Kernel B: the serial decision scan. grid = B, block = 32 (one warp).
// ---------------------------------------------------------------------------
__device__ __forceinline__ float exact_d2(const float* __restrict__ data,
                                          int b, int i, int ind, int lid)
{
    const float4* xi = (const float4*)(data + ((size_t)b * TT + i)   * DD);
    const float4* xr = (const float4*)(data + ((size_t)b * TT + ind) * DD);
    float a = 0.f;
    #pragma unroll
    for (int k = 0; k < 4; ++k) {
        float4 p = xi[k * 32 + lid], q = xr[k * 32 + lid];
        float dx = p.x - q.x, dy = p.y - q.y, dz = p.z - q.z, dw = p.w - q.w;
        a = fmaf(dx, dx, fmaf(dy, dy, fmaf(dz, dz, fmaf(dw, dw, a))));
    }
    #pragma unroll
    for (int m = 16; m; m >>= 1) a += __shfl_xor_sync(0xffffffffu, a, m);
    return a;
}

__global__ void __launch_bounds__(32, 1)
kB(const float* __restrict__ data, const float* __restrict__ thr_p,
   float* __restrict__ out_flags)
{
    __shared__ float D2s[TT * KJ + 64];   // + pad for clamped speculative reads
    __shared__ float tab[TT];             // (thr * factor(f))^2, sign-safe

    const int b   = blockIdx.x;
    const int lid = threadIdx.x;
    const float thr = thr_p[0];

    {
        const float4* src = (const float4*)&g_D2[(size_t)b * TT * KJ];
        float4* dst = (float4*)D2s;
        for (int s = lid; s < TT * KJ / 4; s += 32) dst[s] = src[s];
        for (int s = lid + TT * KJ / 4; s < (TT * KJ + 64) / 4; s += 32)
            dst[s] = make_float4(0.f, 0.f, 0.f, 0.f);
    }
    for (int t = lid; t < TT; t += 32) {
        float a   = fminf(fmaxf((float)t - 1.0f, -80.0f), 80.0f);
        float te  = thr * (1.9f / (1.0f + expf(a)) + 0.4f);
        tab[t] = (te >= 0.0f) ? te * te : -1.0f;   // compare dist^2 > te^2
    }
    __syncwarp();
    __syncthreads();

    float* flags = out_flags + (size_t)b * NS;
    int*   indg  = &g_ind[(size_t)b * TT];

    bool  P = true;          // pseudo "boundary before step 1" => rep = x_0
    int   j = 0, ind = 0;
    float altd = 0.f, altt = 0.f;
    const float te0 = tab[0];
    const float te1 = tab[1];

    int i = 1;
    for (int c = 0; c < 124; ++c) {        // covers i = 1 .. 992
        const bool Pc = P; const int jc = j, indc = ind, ic = i;
        float fbuf[8]; int ibuf[8];
        int bad = 0;
        #pragma unroll
        for (int s = 0; s < 8; ++s, ++i) {
            const float d1   = D2s[i * KJ];              // dist if boundary fired
            const float dist = P ? d1  : altd;
            const float te   = P ? te0 : altt;
            const bool  Pn   = dist > te;
            const int   jn   = P ? 1 : j + 1;
            const int   indn = P ? (i - 1) : ind;
            bad |= ((!P) && (j >= KJ)) ? 1 : 0;
            // 2-deep speculative prefetch for step i+1 (addresses use only j).
            const int jo = (j < 14) ? j : 14;            // clamp (mem safety)
            const float altd_n = P ? D2s[(i + 1) * KJ + 1]
                                   : D2s[(i + 1) * KJ + jo + 1];
            const float altt_n = P ? te1 : tab[j + 1];
            fbuf[s] = Pn ? 1.0f : 0.0f;
            ibuf[s] = indn;
            P = Pn; j = jn; ind = indn; altd = altd_n; altt = altt_n;
        }
        if (bad) {
            // Rollback + exact replay of this chunk.
            P = Pc; j = jc; ind = indc; i = ic;
            for (int s = 0; s < 8; ++s, ++i) {
                const int jn   = P ? 1 : j + 1;
                const int indn = P ? (i - 1) : ind;
                float dist;
                if (jn <= KJ) dist = D2s[i * KJ + (jn - 1)];
                else          dist = exact_d2(data, b, i, indn, lid);
                const float te = tab[jn - 1];
                P = dist > te;
                if (lid == 0) { flags[i - 1] = P ? 1.f : 0.f; indg[i - 1] = indn; }
                j = jn; ind = indn;
            }
            // Rebuild pipeline regs for next chunk (used only if !P).
            const int jo = (j < 14) ? j : 14;
            altd = D2s[i * KJ + jo];
            altt = tab[j];
        } else if (lid == 0) {
            #pragma unroll
            for (int s = 0; s < 8; ++s) {
                flags[ic - 1 + s] = fbuf[s];
                indg [ic - 1 + s] = ibuf[s];
            }
        }
    }
    // Tail: i = 993 .. 999 (exact mode).
    for (; i <= NS; ++i) {
        const int jn   = P ? 1 : j + 1;
        const int indn = P ? (i - 1) : ind;
        float dist;
        if (jn <= KJ) dist = D2s[i * KJ + (jn - 1)];
        else          dist = exact_d2(data, b, i, indn, lid);
        const float te = tab[jn - 1];
        P = dist > te;
        if (lid == 0) { flags[i - 1] = P ? 1.f : 0.f; indg[i - 1] = indn; }
        j = jn; ind = indn;
    }
}

// ---------------------------------------------------------------------------
// Kernel C: segment means. One warp per output row.
// ---------------------------------------------------------------------------
__global__ void __launch_bounds__(256, 1)
kC(const float* __restrict__ data, const float* __restrict__ flags_in,
   float* __restrict__ out_means, int B)
{
    const int r   = blockIdx.x * 8 + (threadIdx.x >> 5);
    const int lid = threadIdx.x & 31;
    if (r >= B * NS) return;
    const int b = r / NS, t = r % NS, i = t + 1;

    float4* orow = (float4*)(out_means + (size_t)r * DD);
    const float fl = flags_in[(size_t)b * NS + t];

    float4 s0 = make_float4(0,0,0,0), s1 = s0, s2 = s0, s3 = s0;
    if (fl > 0.5f) {
        const int ind = g_ind[(size_t)b * TT + t];
        const int len = i - ind;
        const float4* dp = (const float4*)(data + (size_t)b * TT * DD);
        for (int k = ind; k < i; ++k) {
            const float4* fp = dp + (size_t)k * 128;
            float4 v;
            v = fp[      lid]; s0.x += v.x; s0.y += v.y; s0.z += v.z; s0.w += v.w;
            v = fp[32  + lid]; s1.x += v.x; s1.y += v.y; s1.z += v.z; s1.w += v.w;
            v = fp[64  + lid]; s2.x += v.x; s2.y += v.y; s2.z += v.z; s2.w += v.w;
            v = fp[96  + lid]; s3.x += v.x; s3.y += v.y; s3.z += v.z; s3.w += v.w;
        }
        const float inv = 1.0f / (float)len;
        s0.x *= inv; s0.y *= inv; s0.z *= inv; s0.w *= inv;
        s1.x *= inv; s1.y *= inv; s1.z *= inv; s1.w *= inv;
        s2.x *= inv; s2.y *= inv; s2.z *= inv; s2.w *= inv;
        s3.x *= inv; s3.y *= inv; s3.z *= inv; s3.w *= inv;
    }
    orow[      lid] = s0;
    orow[32  + lid] = s1;
    orow[64  + lid] = s2;
    orow[96  + lid] = s3;
}

// ---------------------------------------------------------------------------
extern "C" void kernel_launch(void* const* d_in, const int* in_sizes, int n_in,
                              void* d_out, int out_size) {
    const float* data = (const float*)d_in[0];
    const float* thr  = (const float*)d_in[1];

    int B = in_sizes[0] / (TT * DD);
    if (B > MAXB) B = MAXB;

    float* means = (float*)d_out;                          // [B, 999, 512]
    float* flags = means + (size_t)B * NS * DD;            // [B, 999]

    (void)n_in; (void)out_size;
    kA<<<B * NCH, 256>>>(data);
    kB<<<B, 32>>>(data, thr, flags);
    kC<<<(B * NS + 7) / 8, 256>>>(data, flags, means, B);
}

// round 4
// speedup vs baseline: 5.4732x; 1.0192x over previous
#include <cuda_runtime.h>
#include <cstdint>

// Problem shape (fixed by the reference): B=32, T=1000, D=512.
#define TT   1000
#define DD   512
#define NS   999         // steps / output rows
#define KJ   4           // max precomputed back-distance (rollback covers >KJ)
#define AC   16          // kernel-A i-chunk
#define NCH  ((NS + AC - 1) / AC)   // 63
#define MAXB 32

// Scratch (no allocations allowed -> __device__ globals).
__device__ float g_D2[MAXB * TT * KJ];   // D2[b][i][j-1] = ||x_i - x_{i-j}||^2
__device__ int   g_ind[MAXB * TT];       // segment-start index per step

// ---------------------------------------------------------------------------
// Kernel A: banded pairwise squared distances, smem-tiled.
// grid = B * NCH, block = 256 (8 warps, 2 i's per warp).
// ---------------------------------------------------------------------------
__global__ void __launch_bounds__(256, 1)
kA(const float* __restrict__ data)
{
    __shared__ float fr[(AC + KJ) * DD];          // 20 frames * 2KB = 40KB
    const int b     = blockIdx.x / NCH;
    const int chunk = blockIdx.x % NCH;
    const int c0    = 1 + chunk * AC;             // first i of this chunk
    const int base  = c0 - KJ;                    // first frame needed (can be <0)

    const float4* dglob = (const float4*)(data + (size_t)b * TT * DD);
    float4* frv = (float4*)fr;
    for (int s = threadIdx.x; s < (AC + KJ) * (DD / 4); s += 256) {
        const int f  = s >> 7;                    // /128 float4 per frame
        const int w  = s & 127;
        const int fi = base + f;
        if (fi >= 0 && fi < TT)
            frv[s] = dglob[(size_t)fi * (DD / 4) + w];
    }
    __syncthreads();

    const int wid = threadIdx.x >> 5, lid = threadIdx.x & 31;
    #pragma unroll
    for (int u = 0; u < 2; ++u) {
        const int ii = wid + u * 8;               // 0..15, warp-uniform
        const int i  = c0 + ii;
        if (i > NS) continue;
        const int si = ii + KJ;                   // smem slot of frame i

        // Lane-interleaved (distances are permutation-invariant over D).
        float4 x0 = frv[si * 128 +       lid];
        float4 x1 = frv[si * 128 + 32  + lid];
        float4 x2 = frv[si * 128 + 64  + lid];
        float4 x3 = frv[si * 128 + 96  + lid];

        float acc[KJ];
        #pragma unroll
        for (int j = 1; j <= KJ; ++j) {
            float a0 = 0.f, a1 = 0.f;
            if (i - j >= 0) {
                const int sj = si - j;
                float4 y;
                y = frv[sj * 128 + lid];
                { float dx=x0.x-y.x, dy=x0.y-y.y, dz=x0.z-y.z, dw=x0.w-y.w;
                  a0 = fmaf(dx,dx,fmaf(dy,dy,0.f)); a1 = fmaf(dz,dz,fmaf(dw,dw,0.f)); }
                y = frv[sj * 128 + 32 + lid];
                { float dx=x1.x-y.x, dy=x1.y-y.y, dz=x1.z-y.z, dw=x1.w-y.w;
                  a0 = fmaf(dx,dx,fmaf(dy,dy,a0)); a1 = fmaf(dz,dz,fmaf(dw,dw,a1)); }
                y = frv[sj * 128 + 64 + lid];
                { float dx=x2.x-y.x, dy=x2.y-y.y, dz=x2.z-y.z, dw=x2.w-y.w;
                  a0 = fmaf(dx,dx,fmaf(dy,dy,a0)); a1 = fmaf(dz,dz,fmaf(dw,dw,a1)); }
                y = frv[sj * 128 + 96 + lid];
                { float dx=x3.x-y.x, dy=x3.y-y.y, dz=x3.z-y.z, dw=x3.w-y.w;
                  a0 = fmaf(dx,dx,fmaf(dy,dy,a0)); a1 = fmaf(dz,dz,fmaf(dw,dw,a1)); }
            }
            acc[j - 1] = a0 + a1;
        }
        #pragma unroll
        for (int m = 16; m; m >>= 1) {
            #pragma unroll
            for (int k = 0; k < KJ; ++k)
                acc[k] += __shfl_xor_sync(0xffffffffu, acc[k], m);
        }
        if (lid == 0) {
            float4* o = (float4*)&g_D2[((size_t)b * TT + i) * KJ];
            o[0] = make_float4(acc[0], acc[1], acc[2], acc[3]);
        }
    }
}

// ---------------------------------------------------------------------------
// Kernel B: the serial decision scan. grid = B, block = 32 (one warp).
// Per-step chain is select-only: the whole 16B distance row for each step is
// loaded 3 steps ahead at a static address; the j-dependent component is
// resolved by a lagged FSEL tree.
// ---------------------------------------------------------------------------
__device__ __forceinline__ float exact_d2(const float* __restrict__ data,
                                          int b, int i, int ind, int lid)
{
    const float4* xi = (const float4*)(data + ((size_t)b * TT + i)   * DD);
    const float4* xr = (const float4*)(data + ((size_t)b * TT + ind) * DD);
    float a = 0.f;
    #pragma unroll
    for (int k = 0; k < 4; ++k) {
        float4 p = xi[k * 32 + lid], q = xr[k * 32 + lid];
        float dx = p.x - q.x, dy = p.y - q.y, dz = p.z - q.z, dw = p.w - q.w;
        a = fmaf(dx, dx, fmaf(dy, dy, fmaf(dz, dz, fmaf(dw, dw, a))));
    }
    #pragma unroll
    for (int m = 16; m; m >>= 1) a += __shfl_xor_sync(0xffffffffu, a, m);
    return a;
}

__global__ void __launch_bounds__(32, 1)
kB(const float* __restrict__ data, const float* __restrict__ thr_p,
   float* __restrict__ out_flags)
{
    __shared__ float4 D2s[TT + 4];        // row i = 4 back-distances of step i
    __shared__ float  tab[TT];            // (thr * factor(f))^2, sign-safe

    const int b   = blockIdx.x;
    const int lid = threadIdx.x;
    const float thr = thr_p[0];

    {
        const float4* src = (const float4*)&g_D2[(size_t)b * TT * KJ];
        for (int s = lid; s < TT; s += 32) D2s[s] = src[s];
        if (lid < 4) D2s[TT + lid] = make_float4(0.f, 0.f, 0.f, 0.f);
    }
    for (int t = lid; t < TT; t += 32) {
        float a   = fminf(fmaxf((float)t - 1.0f, -80.0f), 80.0f);
        float te  = thr * (1.9f / (1.0f + expf(a)) + 0.4f);
        tab[t] = (te >= 0.0f) ? te * te : -1.0f;   // compare dist^2 > te^2
    }
    __syncthreads();

    float* flags = out_flags + (size_t)b * NS;
    int*   indg  = &g_ind[(size_t)b * TT];

    const float tab0 = tab[0], tab1 = tab[1], tab2 = tab[2], tab3 = tab[3];

    bool  P = true;          // pseudo "boundary before step 1" => rep = x_0
    int   j = 0, ind = 0;
    float alt = 0.f, talt = 0.f;           // unused while P==true

    // 3-deep static row pipeline: r0=row_i, r1=row_{i+1}, r2=row_{i+2}.
    float4 r0 = D2s[1], r1 = D2s[2], r2 = D2s[3];

    int i = 1;
    for (int c = 0; c < 124; ++c) {        // covers i = 1 .. 992
        const bool Pc = P; const int jc = j, indc = ind, ic = i;
        float fbuf[8]; int ibuf[8];
        int bad = 0;
        #pragma unroll
        for (int s = 0; s < 8; ++s, ++i) {
            const float d    = P ? r0.x  : alt;     // back-dist 1 vs j_old+1
            const float te   = P ? tab0  : talt;
            const bool  Pn   = d > te;
            const int   jn   = P ? 1 : j + 1;
            const int   indn = P ? (i - 1) : ind;
            bad |= ((!P) && (j >= KJ)) ? 1 : 0;

            // Lagged resolve for step i+1 (valid for jn in {1,2,3}; jn>=4
            // mis-selects but the use is then flagged bad -> exact replay).
            const float alt_n  = (jn == 1) ? r1.y : ((jn == 2) ? r1.z : r1.w);
            const float talt_n = (jn == 1) ? tab1 : ((jn == 2) ? tab2 : tab3);

            fbuf[s] = Pn ? 1.0f : 0.0f;
            ibuf[s] = indn;

            // Rotate pipeline, prefetch row i+3 (static address).
            r0 = r1; r1 = r2; r2 = D2s[i + 3];

            P = Pn; j = jn; ind = indn; alt = alt_n; talt = talt_n;
        }
        if (bad) {
            // Rollback + exact replay of this chunk.
            P = Pc; j = jc; ind = indc; i = ic;
            for (int s = 0; s < 8; ++s, ++i) {
                const int jn   = P ? 1 : j + 1;
                const int indn = P ? (i - 1) : ind;
                float dist;
                if (jn <= KJ) {
                    const float4 row = D2s[i];
                    dist = (jn == 1) ? row.x : (jn == 2) ? row.y
                         : (jn == 3) ? row.z : row.w;
                } else {
                    dist = exact_d2(data, b, i, indn, lid);
                }
                const float te = tab[jn - 1];
                P = dist > te;
                if (lid == 0) { flags[i - 1] = P ? 1.f : 0.f; indg[i - 1] = indn; }
                j = jn; ind = indn;
            }
            // Rebuild the pipeline + lagged values for the next chunk.
            r0 = D2s[i]; r1 = D2s[i + 1]; r2 = D2s[i + 2];
            alt  = (j == 1) ? r0.y : ((j == 2) ? r0.z : r0.w);
            talt = tab[(j < TT - 1) ? j : TT - 1];
        } else if (lid == 0) {
            #pragma unroll
            for (int s = 0; s < 8; ++s) {
                flags[ic - 1 + s] = fbuf[s];
                indg [ic - 1 + s] = ibuf[s];
            }
        }
    }
    // Tail: i = 993 .. 999 (exact mode).
    for (; i <= NS; ++i) {
        const int jn   = P ? 1 : j + 1;
        const int indn = P ? (i - 1) : ind;
        float dist;
        if (jn <= KJ) {
            const float4 row = D2s[i];
            dist = (jn == 1) ? row.x : (jn == 2) ? row.y
                 : (jn == 3) ? row.z : row.w;
        } else {
            dist = exact_d2(data, b, i, indn, lid);
        }
        const float te = tab[jn - 1];
        P = dist > te;
        if (lid == 0) { flags[i - 1] = P ? 1.f : 0.f; indg[i - 1] = indn; }
        j = jn; ind = indn;
    }
}

// ---------------------------------------------------------------------------
// Kernel C: segment means. One warp per output row.
// ---------------------------------------------------------------------------
__global__ void __launch_bounds__(256, 1)
kC(const float* __restrict__ data, const float* __restrict__ flags_in,
   float* __restrict__ out_means, int B)
{
    const int r   = blockIdx.x * 8 + (threadIdx.x >> 5);
    const int lid = threadIdx.x & 31;
    if (r >= B * NS) return;
    const int b = r / NS, t = r % NS, i = t + 1;

    float4* orow = (float4*)(out_means + (size_t)r * DD);
    const float fl = flags_in[(size_t)b * NS + t];

    float4 s0 = make_float4(0,0,0,0), s1 = s0, s2 = s0, s3 = s0;
    if (fl > 0.5f) {
        const int ind = g_ind[(size_t)b * TT + t];
        const int len = i - ind;
        const float4* dp = (const float4*)(data + (size_t)b * TT * DD);
        for (int k = ind; k < i; ++k) {
            const float4* fp = dp + (size_t)k * 128;
            float4 v;
            v = fp[      lid]; s0.x += v.x; s0.y += v.y; s0.z += v.z; s0.w += v.w;
            v = fp[32  + lid]; s1.x += v.x; s1.y += v.y; s1.z += v.z; s1.w += v.w;
            v = fp[64  + lid]; s2.x += v.x; s2.y += v.y; s2.z += v.z; s2.w += v.w;
            v = fp[96  + lid]; s3.x += v.x; s3.y += v.y; s3.z += v.z; s3.w += v.w;
        }
        const float inv = 1.0f / (float)len;
        s0.x *= inv; s0.y *= inv; s0.z *= inv; s0.w *= inv;
        s1.x *= inv; s1.y *= inv; s1.z *= inv; s1.w *= inv;
        s2.x *= inv; s2.y *= inv; s2.z *= inv; s2.w *= inv;
        s3.x *= inv; s3.y *= inv; s3.z *= inv; s3.w *= inv;
    }
    orow[      lid] = s0;
    orow[32  + lid] = s1;
    orow[64  + lid] = s2;
    orow[96  + lid] = s3;
}

// ---------------------------------------------------------------------------
extern "C" void kernel_launch(void* const* d_in, const int* in_sizes, int n_in,
                              void* d_out, int out_size) {
    const float* data = (const float*)d_in[0];
    const float* thr  = (const float*)d_in[1];

    int B = in_sizes[0] / (TT * DD);
    if (B > MAXB) B = MAXB;

    float* means = (float*)d_out;                          // [B, 999, 512]
    float* flags = means + (size_t)B * NS * DD;            // [B, 999]

    (void)n_in; (void)out_size;
    kA<<<B * NCH, 256>>>(data);
    kB<<<B, 32>>>(data, thr, flags);
    kC<<<(B * NS + 7) / 8, 256>>>(data, flags, means, B);
}